// round 10
// baseline (speedup 1.0000x reference)
#include <cuda_runtime.h>
#include <cuda_fp16.h>
#include <math.h>
#include <cstdint>

// Problem constants (fixed by dataset)
#define B_C   4
#define L_C   2048
#define EMB_C 1024
#define HEADS_C 16
#define DH    64
#define MROWS (B_C * L_C)          // 8192
#define SCALE_C 0.125f             // 1/sqrt(64)

// ---------------------------------------------------------------------------
// Scratch (allocation-free rule: __device__ globals)
// ---------------------------------------------------------------------------
__device__ float g_q[MROWS * EMB_C];
__device__ float g_k[MROWS * EMB_C];
__device__ float g_v[MROWS * EMB_C];
__device__ float g_att[MROWS * EMB_C];
__device__ __half g_wthi[4 * EMB_C * EMB_C];  // W^T split (hi) [slot][N,K]
__device__ __half g_wtlo[4 * EMB_C * EMB_C];  // W^T split (lo) [slot][N,K]

// ---------------------------------------------------------------------------
// Warp-MMA helpers (arch-portable PTX: ldmatrix + mma.sync m16n8k16 fp16)
// ---------------------------------------------------------------------------
__device__ __forceinline__ uint32_t smem_u32(const void* p) {
    uint32_t a;
    asm("{ .reg .u64 t; cvta.to.shared.u64 t, %1; cvt.u32.u64 %0, t; }"
        : "=r"(a) : "l"(p));
    return a;
}
__device__ __forceinline__ void ldsm4(uint32_t* r, uint32_t addr) {
    asm volatile("ldmatrix.sync.aligned.m8n8.x4.shared.b16 {%0,%1,%2,%3}, [%4];"
                 : "=r"(r[0]), "=r"(r[1]), "=r"(r[2]), "=r"(r[3]) : "r"(addr));
}
__device__ __forceinline__ void ldsm4t(uint32_t* r, uint32_t addr) {
    asm volatile("ldmatrix.sync.aligned.m8n8.x4.trans.shared.b16 {%0,%1,%2,%3}, [%4];"
                 : "=r"(r[0]), "=r"(r[1]), "=r"(r[2]), "=r"(r[3]) : "r"(addr));
}
__device__ __forceinline__ void mma16816(float* c, const uint32_t* a, const uint32_t* b) {
    asm volatile(
        "mma.sync.aligned.m16n8k16.row.col.f32.f16.f16.f32 "
        "{%0,%1,%2,%3}, {%4,%5,%6,%7}, {%8,%9}, {%0,%1,%2,%3};"
        : "+f"(c[0]), "+f"(c[1]), "+f"(c[2]), "+f"(c[3])
        : "r"(a[0]), "r"(a[1]), "r"(a[2]), "r"(a[3]), "r"(b[0]), "r"(b[1]));
}
__device__ __forceinline__ void cpasync16(uint32_t saddr, const void* gptr) {
    asm volatile("cp.async.cg.shared.global [%0], [%1], 16;"
                 :: "r"(saddr), "l"(gptr) : "memory");
}
#define CP_COMMIT() asm volatile("cp.async.commit_group;" ::: "memory")
#define CP_WAIT0()  asm volatile("cp.async.wait_group 0;" ::: "memory")
#define CP_WAIT1()  asm volatile("cp.async.wait_group 1;" ::: "memory")

// pack two fp32 into one fp16x2
__device__ __forceinline__ uint32_t pack2h(float a, float b) {
    __half2 h = __floats2half2_rn(a, b);
    return *(uint32_t*)&h;
}
// split two fp32 into packed fp16x2 hi and lo parts
__device__ __forceinline__ void split2h(float a, float b, uint32_t& hp, uint32_t& lp) {
    __half ha = __float2half_rn(a), hb = __float2half_rn(b);
    __half la = __float2half_rn(a - __half2float(ha));
    __half lb = __float2half_rn(b - __half2float(hb));
    __half2 h2 = __halves2half2(ha, hb), l2 = __halves2half2(la, lb);
    hp = *(uint32_t*)&h2;
    lp = *(uint32_t*)&l2;
}

// ---------------------------------------------------------------------------
// weight transpose + split, all 4 weights in one launch (slot = blockIdx.z)
// ---------------------------------------------------------------------------
__global__ __launch_bounds__(256)
void wsplit_all_kernel(const float* __restrict__ W0, const float* __restrict__ W1,
                       const float* __restrict__ W2, const float* __restrict__ W3,
                       __half* __restrict__ hi, __half* __restrict__ lo) {
    __shared__ float t[32][33];
    const int z = blockIdx.z;
    const float* W = (z == 0) ? W0 : (z == 1) ? W1 : (z == 2) ? W2 : W3;
    __half* hz = hi + (size_t)z * EMB_C * EMB_C;
    __half* lz = lo + (size_t)z * EMB_C * EMB_C;
    int tx = threadIdx.x, ty = threadIdx.y;           // 32 x 8
    int n0 = blockIdx.x * 32, k0 = blockIdx.y * 32;
#pragma unroll
    for (int r = ty; r < 32; r += 8)
        t[r][tx] = W[(size_t)(k0 + r) * EMB_C + n0 + tx];
    __syncthreads();
#pragma unroll
    for (int r = ty; r < 32; r += 8) {
        float v = t[tx][r];                           // W[k0+tx][n0+r]
        __half h = __float2half_rn(v);
        size_t o = (size_t)(n0 + r) * EMB_C + k0 + tx;
        hz[o] = h;
        lz[o] = __float2half_rn(v - __half2float(h));
    }
}

// ---------------------------------------------------------------------------
// Fused mma.sync GEMM, batched over blockIdx.z (selects A/bias/C/weight-slot).
// C[M,N] = A[M,K](fp32 -> fp16 in-kernel) @ (Whi+Wlo)^T + bias   [2 products]
// CTA tile 128x128, BK=32, 8 warps. B: 3-stage cp.async pipeline.
// A: register-staged 2-stage, single fp16.
// __launch_bounds__(256,2): 2 CTAs/SM.
// ---------------------------------------------------------------------------
#define LDS_T 40
#define TILE_E (128 * LDS_T)
#define GEMM_SMEM_B (8 * TILE_E * 2)   // sA 2 + sB 6 tiles = 81920 bytes

__global__ __launch_bounds__(256, 2)
void gemm_batch_kernel(const float* __restrict__ A0, const float* __restrict__ A1,
                       const float* __restrict__ A2,
                       const __half* __restrict__ whi_all,
                       const __half* __restrict__ wlo_all,
                       const float* __restrict__ b0, const float* __restrict__ b1,
                       const float* __restrict__ b2,
                       float* __restrict__ C0, float* __restrict__ C1,
                       float* __restrict__ C2, int wslot0) {
    extern __shared__ __half smbf[];
    __half* sA = smbf;                 // 2 x TILE_E (2 bufs, single fp16)
    __half* sB = smbf + 2 * TILE_E;    // 6 x TILE_E (3 stages x hi/lo)

    const int z = blockIdx.z;
    const float* A    = (z == 0) ? A0 : (z == 1) ? A1 : A2;
    const float* bias = (z == 0) ? b0 : (z == 1) ? b1 : b2;
    float* C          = (z == 0) ? C0 : (z == 1) ? C1 : C2;
    const size_t woff = (size_t)(wslot0 + z) * EMB_C * EMB_C;
    const __half* Bhi = whi_all + woff;
    const __half* Blo = wlo_all + woff;
    const int Kd = EMB_C, Nd = EMB_C;

    const int tid = threadIdx.x;
    const int lane = tid & 31;
    const int wid = tid >> 5;
    const int warp_m = wid & 1;
    const int warp_n = wid >> 1;
    const int m0 = blockIdx.y * 128;
    const int n0 = blockIdx.x * 128;

    float acc[4][4][4];
#pragma unroll
    for (int mi = 0; mi < 4; mi++)
#pragma unroll
        for (int ni = 0; ni < 4; ni++)
#pragma unroll
            for (int r = 0; r < 4; r++) acc[mi][ni][r] = 0.f;

    const int a_row = (lane & 15);
    const int a_co  = (lane >> 4) << 3;
    const int b_rsel = (lane >> 4);
    const int b_row  = (lane & 7);
    const int b_co   = ((lane >> 3) & 1) << 3;

    const int st_row = tid >> 1;
    const int st_c0  = (tid & 1) << 4;

    float4 areg[4];
    const int nch = Kd / 32;

    // B-stage issue helper (chunk c -> stage c%3)
    auto issueB = [&](int c) {
        int stage = c - (c / 3) * 3;
        int k0 = c * 32;
#pragma unroll
        for (int t = 0; t < 4; t++) {
            int i = tid + t * 256;
            int sp = i >> 9, rem = i & 511, row = rem >> 2, seg = (rem & 3) << 3;
            const __half* src = (sp ? Blo : Bhi) + (size_t)(n0 + row) * Kd + k0 + seg;
            cpasync16(smem_u32(sB + (stage * 2 + sp) * TILE_E + row * LDS_T + seg), src);
        }
        CP_COMMIT();
    };

    // ---- prologue: B stages for chunks 0,1; A chunk 0 ----
    issueB(0);
    issueB(1);
    {
        const float* asrc = A + (size_t)(m0 + st_row) * Kd + st_c0;
#pragma unroll
        for (int j = 0; j < 4; j++) areg[j] = *(const float4*)(asrc + j * 4);
#pragma unroll
        for (int j = 0; j < 4; j++)
            *(uint2*)&sA[0 * TILE_E + st_row * LDS_T + st_c0 + j * 4] =
                make_uint2(pack2h(areg[j].x, areg[j].y), pack2h(areg[j].z, areg[j].w));
    }

    for (int chunk = 0; chunk < nch; chunk++) {
        const int cur = chunk & 1;
        const int nxt = cur ^ 1;
        const int stage = chunk - (chunk / 3) * 3;
        const bool has_next = (chunk + 1) < nch;

        if (chunk == nch - 1) { CP_WAIT0(); } else { CP_WAIT1(); }
        __syncthreads();

        if (chunk + 2 < nch) issueB(chunk + 2);
        if (has_next) {
            const float* asrc = A + (size_t)(m0 + st_row) * Kd + (chunk + 1) * 32 + st_c0;
#pragma unroll
            for (int j = 0; j < 4; j++) areg[j] = *(const float4*)(asrc + j * 4);
        }

        // ---- compute from sA[cur], sB[stage] ----
        const __half* cA  = sA + cur * TILE_E;
        const __half* cBh = sB + (stage * 2 + 0) * TILE_E;
        const __half* cBl = sB + (stage * 2 + 1) * TILE_E;
#pragma unroll
        for (int ks = 0; ks < 2; ks++) {
            uint32_t bf[2][4][2];
#pragma unroll
            for (int np = 0; np < 2; np++) {
                int rowe = (warp_n * 32 + (np * 2 + b_rsel) * 8 + b_row) * LDS_T
                           + ks * 16 + b_co;
                uint32_t r4[4];
                ldsm4(r4, smem_u32(cBh) + rowe * 2);
                bf[0][np * 2 + 0][0] = r4[0]; bf[0][np * 2 + 0][1] = r4[1];
                bf[0][np * 2 + 1][0] = r4[2]; bf[0][np * 2 + 1][1] = r4[3];
                ldsm4(r4, smem_u32(cBl) + rowe * 2);
                bf[1][np * 2 + 0][0] = r4[0]; bf[1][np * 2 + 0][1] = r4[1];
                bf[1][np * 2 + 1][0] = r4[2]; bf[1][np * 2 + 1][1] = r4[3];
            }
#pragma unroll
            for (int mi = 0; mi < 4; mi++) {
                uint32_t af[4];
                int rowe = (warp_m * 64 + mi * 16 + a_row) * LDS_T + ks * 16 + a_co;
                ldsm4(af, smem_u32(cA) + rowe * 2);
#pragma unroll
                for (int ni = 0; ni < 4; ni++) {
                    mma16816(acc[mi][ni], af, bf[0][ni]);  // a*hi
                    mma16816(acc[mi][ni], af, bf[1][ni]);  // a*lo
                }
            }
        }

        if (has_next) {
#pragma unroll
            for (int j = 0; j < 4; j++)
                *(uint2*)&sA[nxt * TILE_E + st_row * LDS_T + st_c0 + j * 4] =
                    make_uint2(pack2h(areg[j].x, areg[j].y), pack2h(areg[j].z, areg[j].w));
        }
    }

    // ---- epilogue: add bias, write fp32 ----
#pragma unroll
    for (int mi = 0; mi < 4; mi++) {
#pragma unroll
        for (int ni = 0; ni < 4; ni++) {
            int col = n0 + warp_n * 32 + ni * 8 + (lane & 3) * 2;
            float2 bv = *(const float2*)&bias[col];
            int r0 = m0 + warp_m * 64 + mi * 16 + (lane >> 2);
            float2 o0 = make_float2(acc[mi][ni][0] + bv.x, acc[mi][ni][1] + bv.y);
            float2 o1 = make_float2(acc[mi][ni][2] + bv.x, acc[mi][ni][3] + bv.y);
            *(float2*)&C[(size_t)r0 * Nd + col] = o0;
            *(float2*)&C[(size_t)(r0 + 8) * Nd + col] = o1;
        }
    }
}

// ---------------------------------------------------------------------------
// Tensor-core flash attention (causal). BM=128, BN=64, D=64, 8 warps.
// Q single fp16; K,V split hi/lo fp16 (2-product MMAs). P single fp16.
// __launch_bounds__(256,2): 2 CTAs/SM.
// ---------------------------------------------------------------------------
#define AT_LDS 72

__global__ __launch_bounds__(256, 2)
void attn_tc_kernel(const float* __restrict__ q, const float* __restrict__ k,
                    const float* __restrict__ v, float* __restrict__ out) {
    __shared__ __align__(16) char sm[4 * 64 * AT_LDS * 2];   // 36864 B
    __half* sKhi = (__half*)sm;
    __half* sKlo = sKhi + 64 * AT_LDS;
    __half* sVhi = sKhi + 2 * 64 * AT_LDS;
    __half* sVlo = sKhi + 3 * 64 * AT_LDS;
    __half* sQ   = sKhi;                 // Q staging overlays (128 rows)

    const int tid = threadIdx.x;
    const int lane = tid & 31;
    const int w = tid >> 5;
    const int quad = lane >> 2;
    const int par2 = (lane & 3) * 2;

    const int m0 = (gridDim.x - 1 - blockIdx.x) * 128;   // heavy tiles first
    const int h  = blockIdx.y;
    const int b  = blockIdx.z;
    const size_t baseOff = (size_t)b * L_C * EMB_C + (size_t)h * DH;
    const float* qb = q + baseOff;
    const float* kb = k + baseOff;
    const float* vb = v + baseOff;

    const uint32_t u_sKhi = smem_u32(sKhi);
    const uint32_t u_sKlo = smem_u32(sKlo);
    const uint32_t u_sVhi = smem_u32(sVhi);
    const uint32_t u_sVlo = smem_u32(sVlo);

    // ---- prologue: stage Q (scaled) as fp16, load fragments ----
    {
        int row = tid >> 1;
        int d0 = (tid & 1) * 32;
        const float* src = qb + (size_t)(m0 + row) * EMB_C + d0;
#pragma unroll
        for (int j = 0; j < 8; j++) {
            float4 g = *(const float4*)(src + j * 4);
            *(uint2*)&sQ[row * AT_LDS + d0 + j * 4] =
                make_uint2(pack2h(g.x * SCALE_C, g.y * SCALE_C),
                           pack2h(g.z * SCALE_C, g.w * SCALE_C));
        }
    }
    __syncthreads();

    uint32_t qf[4][4];
    {
        int r = w * 16 + (lane & 15);
        int c = (lane >> 4) * 8;
#pragma unroll
        for (int kc = 0; kc < 4; kc++)
            ldsm4(qf[kc], smem_u32(sQ) + (r * AT_LDS + kc * 16 + c) * 2);
    }
    __syncthreads();

    float oacc[8][4];
#pragma unroll
    for (int nt = 0; nt < 8; nt++)
#pragma unroll
        for (int r = 0; r < 4; r++) oacc[nt][r] = 0.f;
    float m_lo = -1e30f, m_hi = -1e30f, l_lo = 0.f, l_hi = 0.f;

    const int row_lo_g = m0 + w * 16 + quad;
    const int warp_max_row = m0 + w * 16 + 15;

    for (int n0 = 0; n0 < m0 + 128; n0 += 64) {
        {
            int row = tid >> 2;
            int d0 = (tid & 3) << 4;
            const float* ksrc = kb + (size_t)(n0 + row) * EMB_C + d0;
            const float* vsrc = vb + (size_t)(n0 + row) * EMB_C + d0;
#pragma unroll
            for (int j = 0; j < 4; j++) {
                float4 gk = *(const float4*)(ksrc + j * 4);
                uint32_t hp0, lp0, hp1, lp1;
                split2h(gk.x, gk.y, hp0, lp0);
                split2h(gk.z, gk.w, hp1, lp1);
                *(uint2*)&sKhi[row * AT_LDS + d0 + j * 4] = make_uint2(hp0, hp1);
                *(uint2*)&sKlo[row * AT_LDS + d0 + j * 4] = make_uint2(lp0, lp1);
                float4 gv = *(const float4*)(vsrc + j * 4);
                split2h(gv.x, gv.y, hp0, lp0);
                split2h(gv.z, gv.w, hp1, lp1);
                *(uint2*)&sVhi[row * AT_LDS + d0 + j * 4] = make_uint2(hp0, hp1);
                *(uint2*)&sVlo[row * AT_LDS + d0 + j * 4] = make_uint2(lp0, lp1);
            }
        }
        __syncthreads();

        if (n0 <= warp_max_row) {
            float sacc[8][4];
#pragma unroll
            for (int nt = 0; nt < 8; nt++)
#pragma unroll
                for (int r = 0; r < 4; r++) sacc[nt][r] = 0.f;

            const int kb_row = ((lane >> 4) & 1) * 8 + (lane & 7);
            const int kb_col = ((lane >> 3) & 1) * 8;
#pragma unroll
            for (int kc = 0; kc < 4; kc++) {
                uint32_t kh[8][2], kl[8][2];
#pragma unroll
                for (int np = 0; np < 4; np++) {
                    uint32_t t4[4];
                    uint32_t off = ((np * 16 + kb_row) * AT_LDS + kc * 16 + kb_col) * 2;
                    ldsm4(t4, u_sKhi + off);
                    kh[np * 2 + 0][0] = t4[0]; kh[np * 2 + 0][1] = t4[1];
                    kh[np * 2 + 1][0] = t4[2]; kh[np * 2 + 1][1] = t4[3];
                    ldsm4(t4, u_sKlo + off);
                    kl[np * 2 + 0][0] = t4[0]; kl[np * 2 + 0][1] = t4[1];
                    kl[np * 2 + 1][0] = t4[2]; kl[np * 2 + 1][1] = t4[3];
                }
#pragma unroll
                for (int nt = 0; nt < 8; nt++) {
                    mma16816(sacc[nt], qf[kc], kh[nt]);
                    mma16816(sacc[nt], qf[kc], kl[nt]);
                }
            }

            if (n0 + 63 > row_lo_g) {
#pragma unroll
                for (int nt = 0; nt < 8; nt++) {
#pragma unroll
                    for (int c = 0; c < 2; c++) {
                        int col = n0 + nt * 8 + par2 + c;
                        if (col > row_lo_g) sacc[nt][c] = -1e30f;
                        if (col > row_lo_g + 8) sacc[nt][2 + c] = -1e30f;
                    }
                }
            } else if (n0 + 63 > row_lo_g + 8) {
#pragma unroll
                for (int nt = 0; nt < 8; nt++)
#pragma unroll
                    for (int c = 0; c < 2; c++) {
                        int col = n0 + nt * 8 + par2 + c;
                        if (col > row_lo_g + 8) sacc[nt][2 + c] = -1e30f;
                    }
            }

            {
                float mx0 = -1e30f, mx1 = -1e30f;
#pragma unroll
                for (int nt = 0; nt < 8; nt++) {
                    mx0 = fmaxf(mx0, fmaxf(sacc[nt][0], sacc[nt][1]));
                    mx1 = fmaxf(mx1, fmaxf(sacc[nt][2], sacc[nt][3]));
                }
                mx0 = fmaxf(mx0, __shfl_xor_sync(0xffffffffu, mx0, 1));
                mx0 = fmaxf(mx0, __shfl_xor_sync(0xffffffffu, mx0, 2));
                mx1 = fmaxf(mx1, __shfl_xor_sync(0xffffffffu, mx1, 1));
                mx1 = fmaxf(mx1, __shfl_xor_sync(0xffffffffu, mx1, 2));
                float mn0 = fmaxf(m_lo, mx0), mn1 = fmaxf(m_hi, mx1);
                float f0 = __expf(m_lo - mn0), f1 = __expf(m_hi - mn1);
                float rs0 = 0.f, rs1 = 0.f;
#pragma unroll
                for (int nt = 0; nt < 8; nt++) {
                    sacc[nt][0] = __expf(sacc[nt][0] - mn0);
                    sacc[nt][1] = __expf(sacc[nt][1] - mn0);
                    sacc[nt][2] = __expf(sacc[nt][2] - mn1);
                    sacc[nt][3] = __expf(sacc[nt][3] - mn1);
                    rs0 += sacc[nt][0] + sacc[nt][1];
                    rs1 += sacc[nt][2] + sacc[nt][3];
                }
                rs0 += __shfl_xor_sync(0xffffffffu, rs0, 1);
                rs0 += __shfl_xor_sync(0xffffffffu, rs0, 2);
                rs1 += __shfl_xor_sync(0xffffffffu, rs1, 1);
                rs1 += __shfl_xor_sync(0xffffffffu, rs1, 2);
                l_lo = l_lo * f0 + rs0;
                l_hi = l_hi * f1 + rs1;
                m_lo = mn0;
                m_hi = mn1;
#pragma unroll
                for (int nt = 0; nt < 8; nt++) {
                    oacc[nt][0] *= f0;
                    oacc[nt][1] *= f0;
                    oacc[nt][2] *= f1;
                    oacc[nt][3] *= f1;
                }
            }

            // ---- PV: P (single fp16 from regs) x V (hi/lo from smem) ----
            const int vb_row = ((lane >> 3) & 1) * 8 + (lane & 7);
            const int vb_col = ((lane >> 4) & 1) * 8;
#pragma unroll
            for (int ks = 0; ks < 4; ks++) {
                uint32_t pa[4];
                pa[0] = pack2h(sacc[2 * ks][0], sacc[2 * ks][1]);
                pa[1] = pack2h(sacc[2 * ks][2], sacc[2 * ks][3]);
                pa[2] = pack2h(sacc[2 * ks + 1][0], sacc[2 * ks + 1][1]);
                pa[3] = pack2h(sacc[2 * ks + 1][2], sacc[2 * ks + 1][3]);

                uint32_t vh[8][2], vl[8][2];
#pragma unroll
                for (int dp = 0; dp < 4; dp++) {
                    uint32_t t4[4];
                    uint32_t off = ((ks * 16 + vb_row) * AT_LDS + dp * 16 + vb_col) * 2;
                    ldsm4t(t4, u_sVhi + off);
                    vh[dp * 2 + 0][0] = t4[0]; vh[dp * 2 + 0][1] = t4[1];
                    vh[dp * 2 + 1][0] = t4[2]; vh[dp * 2 + 1][1] = t4[3];
                    ldsm4t(t4, u_sVlo + off);
                    vl[dp * 2 + 0][0] = t4[0]; vl[dp * 2 + 0][1] = t4[1];
                    vl[dp * 2 + 1][0] = t4[2]; vl[dp * 2 + 1][1] = t4[3];
                }
#pragma unroll
                for (int nt = 0; nt < 8; nt++) {
                    mma16816(oacc[nt], pa, vh[nt]);
                    mma16816(oacc[nt], pa, vl[nt]);
                }
            }
        }
        __syncthreads();
    }

    float inv0 = 1.f / l_lo, inv1 = 1.f / l_hi;
    float* ob = out + baseOff;
    const int r0 = m0 + w * 16 + quad;
#pragma unroll
    for (int nt = 0; nt < 8; nt++) {
        int col = nt * 8 + par2;
        *(float2*)&ob[(size_t)r0 * EMB_C + col] =
            make_float2(oacc[nt][0] * inv0, oacc[nt][1] * inv0);
        *(float2*)&ob[(size_t)(r0 + 8) * EMB_C + col] =
            make_float2(oacc[nt][2] * inv1, oacc[nt][3] * inv1);
    }
}

// ---------------------------------------------------------------------------
// launch
// ---------------------------------------------------------------------------
extern "C" void kernel_launch(void* const* d_in, const int* in_sizes, int n_in,
                              void* d_out, int out_size) {
    const float* Q  = (const float*)d_in[0];
    const float* K  = (const float*)d_in[1];
    const float* V  = (const float*)d_in[2];
    const float* WQ = (const float*)d_in[3];
    const float* bQ = (const float*)d_in[4];
    const float* WK = (const float*)d_in[5];
    const float* bK = (const float*)d_in[6];
    const float* WV = (const float*)d_in[7];
    const float* bV = (const float*)d_in[8];
    const float* WO = (const float*)d_in[9];
    const float* bO = (const float*)d_in[10];
    float* out = (float*)d_out;

    void *pq, *pk, *pv, *pa, *pwh, *pwl;
    cudaGetSymbolAddress(&pq, g_q);
    cudaGetSymbolAddress(&pk, g_k);
    cudaGetSymbolAddress(&pv, g_v);
    cudaGetSymbolAddress(&pa, g_att);
    cudaGetSymbolAddress(&pwh, g_wthi);
    cudaGetSymbolAddress(&pwl, g_wtlo);
    __half* whi = (__half*)pwh;
    __half* wlo = (__half*)pwl;
    float* fq = (float*)pq;
    float* fk = (float*)pk;
    float* fv = (float*)pv;
    float* fa = (float*)pa;

    cudaFuncSetAttribute(gemm_batch_kernel,
                         cudaFuncAttributeMaxDynamicSharedMemorySize, GEMM_SMEM_B);

    // split all 4 weight matrices (slots: 0=WQ, 1=WK, 2=WV, 3=WO)
    wsplit_all_kernel<<<dim3(EMB_C / 32, EMB_C / 32, 4), dim3(32, 8)>>>(
        WQ, WK, WV, WO, whi, wlo);

    // Q, K, V projections in one batched launch
    gemm_batch_kernel<<<dim3(EMB_C / 128, MROWS / 128, 3), 256, GEMM_SMEM_B>>>(
        Q, K, V, whi, wlo, bQ, bK, bV, fq, fk, fv, 0);

    // attention (tensor core)
    dim3 ga(L_C / 128, HEADS_C, B_C);   // (16, 16, 4)
    attn_tc_kernel<<<ga, 256>>>(fq, fk, fv, fa);

    // O projection (slot 3)
    gemm_batch_kernel<<<dim3(EMB_C / 128, MROWS / 128, 1), 256, GEMM_SMEM_B>>>(
        fa, fa, fa, whi, wlo, bO, bO, bO, out, out, out, 3);
}

// round 11
// speedup vs baseline: 1.2730x; 1.2730x over previous
#include <cuda_runtime.h>
#include <cuda_bf16.h>
#include <math.h>
#include <cstdint>

// Problem constants (fixed by dataset)
#define B_C   4
#define L_C   2048
#define EMB_C 1024
#define HEADS_C 16
#define DH    64
#define MROWS (B_C * L_C)          // 8192
#define SCALE_C 0.125f             // 1/sqrt(64)

// ---------------------------------------------------------------------------
// Scratch (allocation-free rule: __device__ globals)
// ---------------------------------------------------------------------------
__device__ float g_q[MROWS * EMB_C];
__device__ float g_k[MROWS * EMB_C];
__device__ float g_v[MROWS * EMB_C];
__device__ float g_att[MROWS * EMB_C];
__device__ __nv_bfloat16 g_wthi[4 * EMB_C * EMB_C];  // W^T split (hi) [slot][N,K]
__device__ __nv_bfloat16 g_wtlo[4 * EMB_C * EMB_C];  // W^T split (lo) [slot][N,K]

// ---------------------------------------------------------------------------
// Warp-MMA helpers (arch-portable PTX: ldmatrix + mma.sync m16n8k16 bf16)
// ---------------------------------------------------------------------------
__device__ __forceinline__ uint32_t smem_u32(const void* p) {
    uint32_t a;
    asm("{ .reg .u64 t; cvta.to.shared.u64 t, %1; cvt.u32.u64 %0, t; }"
        : "=r"(a) : "l"(p));
    return a;
}
__device__ __forceinline__ void ldsm4(uint32_t* r, uint32_t addr) {
    asm volatile("ldmatrix.sync.aligned.m8n8.x4.shared.b16 {%0,%1,%2,%3}, [%4];"
                 : "=r"(r[0]), "=r"(r[1]), "=r"(r[2]), "=r"(r[3]) : "r"(addr));
}
__device__ __forceinline__ void ldsm4t(uint32_t* r, uint32_t addr) {
    asm volatile("ldmatrix.sync.aligned.m8n8.x4.trans.shared.b16 {%0,%1,%2,%3}, [%4];"
                 : "=r"(r[0]), "=r"(r[1]), "=r"(r[2]), "=r"(r[3]) : "r"(addr));
}
__device__ __forceinline__ void mma16816(float* c, const uint32_t* a, const uint32_t* b) {
    asm volatile(
        "mma.sync.aligned.m16n8k16.row.col.f32.bf16.bf16.f32 "
        "{%0,%1,%2,%3}, {%4,%5,%6,%7}, {%8,%9}, {%0,%1,%2,%3};"
        : "+f"(c[0]), "+f"(c[1]), "+f"(c[2]), "+f"(c[3])
        : "r"(a[0]), "r"(a[1]), "r"(a[2]), "r"(a[3]), "r"(b[0]), "r"(b[1]));
}
__device__ __forceinline__ void cpasync16(uint32_t saddr, const void* gptr) {
    asm volatile("cp.async.cg.shared.global [%0], [%1], 16;"
                 :: "r"(saddr), "l"(gptr) : "memory");
}
#define CP_COMMIT() asm volatile("cp.async.commit_group;" ::: "memory")
#define CP_WAIT0()  asm volatile("cp.async.wait_group 0;" ::: "memory")
#define CP_WAIT1()  asm volatile("cp.async.wait_group 1;" ::: "memory")

// split two fp32 into packed bf16x2 hi and lo parts
__device__ __forceinline__ void split2(float a, float b, uint32_t& hp, uint32_t& lp) {
    __nv_bfloat16 ha = __float2bfloat16(a), hb = __float2bfloat16(b);
    __nv_bfloat16 la = __float2bfloat16(a - __bfloat162float(ha));
    __nv_bfloat16 lb = __float2bfloat16(b - __bfloat162float(hb));
    __nv_bfloat162 h2(ha, hb), l2(la, lb);
    hp = *(uint32_t*)&h2;
    lp = *(uint32_t*)&l2;
}

// ---------------------------------------------------------------------------
// weight transpose + split, all 4 weights in one launch (slot = blockIdx.z)
// ---------------------------------------------------------------------------
__global__ __launch_bounds__(256)
void wsplit_all_kernel(const float* __restrict__ W0, const float* __restrict__ W1,
                       const float* __restrict__ W2, const float* __restrict__ W3,
                       __nv_bfloat16* __restrict__ hi, __nv_bfloat16* __restrict__ lo) {
    __shared__ float t[32][33];
    const int z = blockIdx.z;
    const float* W = (z == 0) ? W0 : (z == 1) ? W1 : (z == 2) ? W2 : W3;
    __nv_bfloat16* hz = hi + (size_t)z * EMB_C * EMB_C;
    __nv_bfloat16* lz = lo + (size_t)z * EMB_C * EMB_C;
    int tx = threadIdx.x, ty = threadIdx.y;           // 32 x 8
    int n0 = blockIdx.x * 32, k0 = blockIdx.y * 32;
#pragma unroll
    for (int r = ty; r < 32; r += 8)
        t[r][tx] = W[(size_t)(k0 + r) * EMB_C + n0 + tx];
    __syncthreads();
#pragma unroll
    for (int r = ty; r < 32; r += 8) {
        float v = t[tx][r];                           // W[k0+tx][n0+r]
        __nv_bfloat16 h = __float2bfloat16(v);
        size_t o = (size_t)(n0 + r) * EMB_C + k0 + tx;
        hz[o] = h;
        lz[o] = __float2bfloat16(v - __bfloat162float(h));
    }
}

// ---------------------------------------------------------------------------
// Fused mma.sync GEMM, batched over blockIdx.z (selects A/bias/C/weight-slot).
// C[M,N] = A[M,K](fp32, split in-kernel) @ (Whi+Wlo)^T + bias  [bf16, 3 products]
// CTA tile 128x128, BK=32, 8 warps. B: 3-stage cp.async pipeline.
// A: register-staged 2-stage with in-register fp32->bf16 hi/lo conversion.
// __launch_bounds__(256,2): 2 CTAs/SM.
// ---------------------------------------------------------------------------
#define LDS_T 40
#define TILE_E (128 * LDS_T)
#define GEMM_SMEM_B (10 * TILE_E * 2)   // sA 4 + sB 6 tiles = 102400 bytes

__global__ __launch_bounds__(256, 2)
void gemm_batch_kernel(const float* __restrict__ A0, const float* __restrict__ A1,
                       const float* __restrict__ A2,
                       const __nv_bfloat16* __restrict__ whi_all,
                       const __nv_bfloat16* __restrict__ wlo_all,
                       const float* __restrict__ b0, const float* __restrict__ b1,
                       const float* __restrict__ b2,
                       float* __restrict__ C0, float* __restrict__ C1,
                       float* __restrict__ C2, int wslot0) {
    extern __shared__ __nv_bfloat16 smbf[];
    __nv_bfloat16* sA = smbf;                 // 4 x TILE_E (2 bufs x hi/lo)
    __nv_bfloat16* sB = smbf + 4 * TILE_E;    // 6 x TILE_E (3 stages x hi/lo)

    const int z = blockIdx.z;
    const float* A    = (z == 0) ? A0 : (z == 1) ? A1 : A2;
    const float* bias = (z == 0) ? b0 : (z == 1) ? b1 : b2;
    float* C          = (z == 0) ? C0 : (z == 1) ? C1 : C2;
    const size_t woff = (size_t)(wslot0 + z) * EMB_C * EMB_C;
    const __nv_bfloat16* Bhi = whi_all + woff;
    const __nv_bfloat16* Blo = wlo_all + woff;
    const int Kd = EMB_C, Nd = EMB_C;

    const int tid = threadIdx.x;
    const int lane = tid & 31;
    const int wid = tid >> 5;
    const int warp_m = wid & 1;
    const int warp_n = wid >> 1;
    const int m0 = blockIdx.y * 128;
    const int n0 = blockIdx.x * 128;

    float acc[4][4][4];
#pragma unroll
    for (int mi = 0; mi < 4; mi++)
#pragma unroll
        for (int ni = 0; ni < 4; ni++)
#pragma unroll
            for (int r = 0; r < 4; r++) acc[mi][ni][r] = 0.f;

    const int a_row = (lane & 15);
    const int a_co  = (lane >> 4) << 3;
    const int b_rsel = (lane >> 4);
    const int b_row  = (lane & 7);
    const int b_co   = ((lane >> 3) & 1) << 3;

    const int st_row = tid >> 1;
    const int st_c0  = (tid & 1) << 4;

    float4 areg[4];
    const int nch = Kd / 32;

    auto issueB = [&](int c) {
        int stage = c - (c / 3) * 3;
        int k0 = c * 32;
#pragma unroll
        for (int t = 0; t < 4; t++) {
            int i = tid + t * 256;
            int sp = i >> 9, rem = i & 511, row = rem >> 2, seg = (rem & 3) << 3;
            const __nv_bfloat16* src = (sp ? Blo : Bhi) + (size_t)(n0 + row) * Kd + k0 + seg;
            cpasync16(smem_u32(sB + (stage * 2 + sp) * TILE_E + row * LDS_T + seg), src);
        }
        CP_COMMIT();
    };

    // ---- prologue: B stages for chunks 0,1; A chunk 0 ----
    issueB(0);
    issueB(1);
    {
        const float* asrc = A + (size_t)(m0 + st_row) * Kd + st_c0;
#pragma unroll
        for (int j = 0; j < 4; j++) areg[j] = *(const float4*)(asrc + j * 4);
#pragma unroll
        for (int j = 0; j < 4; j++) {
            uint32_t hp0, lp0, hp1, lp1;
            split2(areg[j].x, areg[j].y, hp0, lp0);
            split2(areg[j].z, areg[j].w, hp1, lp1);
            *(uint2*)&sA[0 * TILE_E + st_row * LDS_T + st_c0 + j * 4] = make_uint2(hp0, hp1);
            *(uint2*)&sA[1 * TILE_E + st_row * LDS_T + st_c0 + j * 4] = make_uint2(lp0, lp1);
        }
    }

    for (int chunk = 0; chunk < nch; chunk++) {
        const int cur = chunk & 1;
        const int nxt = cur ^ 1;
        const int stage = chunk - (chunk / 3) * 3;
        const bool has_next = (chunk + 1) < nch;

        if (chunk == nch - 1) { CP_WAIT0(); } else { CP_WAIT1(); }
        __syncthreads();

        if (chunk + 2 < nch) issueB(chunk + 2);
        if (has_next) {
            const float* asrc = A + (size_t)(m0 + st_row) * Kd + (chunk + 1) * 32 + st_c0;
#pragma unroll
            for (int j = 0; j < 4; j++) areg[j] = *(const float4*)(asrc + j * 4);
        }

        const __nv_bfloat16* cAh = sA + (cur * 2 + 0) * TILE_E;
        const __nv_bfloat16* cAl = sA + (cur * 2 + 1) * TILE_E;
        const __nv_bfloat16* cBh = sB + (stage * 2 + 0) * TILE_E;
        const __nv_bfloat16* cBl = sB + (stage * 2 + 1) * TILE_E;
#pragma unroll
        for (int ks = 0; ks < 2; ks++) {
            uint32_t bf[2][4][2];
#pragma unroll
            for (int np = 0; np < 2; np++) {
                int rowe = (warp_n * 32 + (np * 2 + b_rsel) * 8 + b_row) * LDS_T
                           + ks * 16 + b_co;
                uint32_t r4[4];
                ldsm4(r4, smem_u32(cBh) + rowe * 2);
                bf[0][np * 2 + 0][0] = r4[0]; bf[0][np * 2 + 0][1] = r4[1];
                bf[0][np * 2 + 1][0] = r4[2]; bf[0][np * 2 + 1][1] = r4[3];
                ldsm4(r4, smem_u32(cBl) + rowe * 2);
                bf[1][np * 2 + 0][0] = r4[0]; bf[1][np * 2 + 0][1] = r4[1];
                bf[1][np * 2 + 1][0] = r4[2]; bf[1][np * 2 + 1][1] = r4[3];
            }
#pragma unroll
            for (int mi = 0; mi < 4; mi++) {
                uint32_t af[2][4];
                int rowe = (warp_m * 64 + mi * 16 + a_row) * LDS_T + ks * 16 + a_co;
                ldsm4(af[0], smem_u32(cAh) + rowe * 2);
                ldsm4(af[1], smem_u32(cAl) + rowe * 2);
#pragma unroll
                for (int ni = 0; ni < 4; ni++) {
                    mma16816(acc[mi][ni], af[0], bf[0][ni]);  // hi*hi
                    mma16816(acc[mi][ni], af[0], bf[1][ni]);  // hi*lo
                    mma16816(acc[mi][ni], af[1], bf[0][ni]);  // lo*hi
                }
            }
        }

        if (has_next) {
#pragma unroll
            for (int j = 0; j < 4; j++) {
                uint32_t hp0, lp0, hp1, lp1;
                split2(areg[j].x, areg[j].y, hp0, lp0);
                split2(areg[j].z, areg[j].w, hp1, lp1);
                *(uint2*)&sA[(nxt * 2 + 0) * TILE_E + st_row * LDS_T + st_c0 + j * 4] =
                    make_uint2(hp0, hp1);
                *(uint2*)&sA[(nxt * 2 + 1) * TILE_E + st_row * LDS_T + st_c0 + j * 4] =
                    make_uint2(lp0, lp1);
            }
        }
    }

    // ---- epilogue: add bias, write fp32 ----
#pragma unroll
    for (int mi = 0; mi < 4; mi++) {
#pragma unroll
        for (int ni = 0; ni < 4; ni++) {
            int col = n0 + warp_n * 32 + ni * 8 + (lane & 3) * 2;
            float2 bv = *(const float2*)&bias[col];
            int r0 = m0 + warp_m * 64 + mi * 16 + (lane >> 2);
            float2 o0 = make_float2(acc[mi][ni][0] + bv.x, acc[mi][ni][1] + bv.y);
            float2 o1 = make_float2(acc[mi][ni][2] + bv.x, acc[mi][ni][3] + bv.y);
            *(float2*)&C[(size_t)r0 * Nd + col] = o0;
            *(float2*)&C[(size_t)(r0 + 8) * Nd + col] = o1;
        }
    }
}

// ---------------------------------------------------------------------------
// Tensor-core flash attention (causal). BM=128, BN=64, D=64, 8 warps.
// bf16 hi/lo 3-product MMAs. K/V raw fp32 staged via 2-stage cp.async
// ping-pong so global latency overlaps compute. 2 CTAs/SM.
// smem: split 36864 B + raw 65536 B = 102400 B (dynamic).
// ---------------------------------------------------------------------------
#define AT_LDS 72
#define AT_SPLIT_B (4 * 64 * AT_LDS * 2)       // 36864
#define AT_RAW_E   (64 * 64)                   // floats per K or V tile
#define AT_SMEM_B  (AT_SPLIT_B + 2 * 2 * AT_RAW_E * 4)  // 102400

__global__ __launch_bounds__(256, 2)
void attn_tc_kernel(const float* __restrict__ q, const float* __restrict__ k,
                    const float* __restrict__ v, float* __restrict__ out) {
    extern __shared__ __align__(16) char sm[];
    __nv_bfloat16* sKhi = (__nv_bfloat16*)sm;
    __nv_bfloat16* sKlo = sKhi + 64 * AT_LDS;
    __nv_bfloat16* sVhi = sKhi + 2 * 64 * AT_LDS;
    __nv_bfloat16* sVlo = sKhi + 3 * 64 * AT_LDS;
    __nv_bfloat16* sQhi = sKhi;                     // Q staging overlays
    __nv_bfloat16* sQlo = sVhi;
    float* sRawK = (float*)(sm + AT_SPLIT_B);       // [stage][64*64]
    float* sRawV = sRawK + 2 * AT_RAW_E;            // [stage][64*64]

    const int tid = threadIdx.x;
    const int lane = tid & 31;
    const int w = tid >> 5;
    const int quad = lane >> 2;
    const int par2 = (lane & 3) * 2;

    const int m0 = (gridDim.x - 1 - blockIdx.x) * 128;   // heavy tiles first
    const int h  = blockIdx.y;
    const int b  = blockIdx.z;
    const size_t baseOff = (size_t)b * L_C * EMB_C + (size_t)h * DH;
    const float* qb = q + baseOff;
    const float* kb = k + baseOff;
    const float* vb = v + baseOff;

    const uint32_t u_sKhi = smem_u32(sKhi);
    const uint32_t u_sKlo = smem_u32(sKlo);
    const uint32_t u_sVhi = smem_u32(sVhi);
    const uint32_t u_sVlo = smem_u32(sVlo);

    const int ntiles = (m0 + 128) / 64;

    // raw prefetch: 64 rows x 64 floats (16 float4/row); 1024 float4 tasks
    auto issueKV = [&](int tile) {
        int stg = tile & 1;
        int n0 = tile * 64;
#pragma unroll
        for (int t = 0; t < 4; t++) {
            int i = tid + t * 256;
            int row = i >> 4, seg = (i & 15) << 2;
            const float* ksrc = kb + (size_t)(n0 + row) * EMB_C + seg;
            const float* vsrc = vb + (size_t)(n0 + row) * EMB_C + seg;
            cpasync16(smem_u32(sRawK + stg * AT_RAW_E + row * 64 + seg), ksrc);
            cpasync16(smem_u32(sRawV + stg * AT_RAW_E + row * 64 + seg), vsrc);
        }
        CP_COMMIT();
    };

    // ---- prologue: issue raw tile 0; stage Q (scaled) hi/lo; Q fragments ----
    issueKV(0);
    {
        int row = tid >> 1;
        int d0 = (tid & 1) * 32;
        const float* src = qb + (size_t)(m0 + row) * EMB_C + d0;
#pragma unroll
        for (int j = 0; j < 8; j++) {
            float4 g = *(const float4*)(src + j * 4);
            uint32_t hp0, lp0, hp1, lp1;
            split2(g.x * SCALE_C, g.y * SCALE_C, hp0, lp0);
            split2(g.z * SCALE_C, g.w * SCALE_C, hp1, lp1);
            *(uint2*)&sQhi[row * AT_LDS + d0 + j * 4] = make_uint2(hp0, hp1);
            *(uint2*)&sQlo[row * AT_LDS + d0 + j * 4] = make_uint2(lp0, lp1);
        }
    }
    __syncthreads();

    uint32_t qfh[4][4], qfl[4][4];
    {
        int r = w * 16 + (lane & 15);
        int c = (lane >> 4) * 8;
#pragma unroll
        for (int kc = 0; kc < 4; kc++) {
            ldsm4(qfh[kc], smem_u32(sQhi) + (r * AT_LDS + kc * 16 + c) * 2);
            ldsm4(qfl[kc], smem_u32(sQlo) + (r * AT_LDS + kc * 16 + c) * 2);
        }
    }

    float oacc[8][4];
#pragma unroll
    for (int nt = 0; nt < 8; nt++)
#pragma unroll
        for (int r = 0; r < 4; r++) oacc[nt][r] = 0.f;
    float m_lo = -1e30f, m_hi = -1e30f, l_lo = 0.f, l_hi = 0.f;

    const int row_lo_g = m0 + w * 16 + quad;
    const int warp_max_row = m0 + w * 16 + 15;

    for (int tile = 0; tile < ntiles; tile++) {
        const int n0 = tile * 64;
        const int stg = tile & 1;

        CP_WAIT0();
        __syncthreads();   // raw[tile] visible to all; prev compute done with split bufs
                           // (also covers Q-fragment loads on tile 0)

        // ---- convert raw fp32 -> split bf16 smem ----
        {
            int row = tid >> 2;
            int d0 = (tid & 3) << 4;
            const float* kraw = sRawK + stg * AT_RAW_E + row * 64 + d0;
            const float* vraw = sRawV + stg * AT_RAW_E + row * 64 + d0;
#pragma unroll
            for (int j = 0; j < 4; j++) {
                float4 gk = *(const float4*)(kraw + j * 4);
                uint32_t hp0, lp0, hp1, lp1;
                split2(gk.x, gk.y, hp0, lp0);
                split2(gk.z, gk.w, hp1, lp1);
                *(uint2*)&sKhi[row * AT_LDS + d0 + j * 4] = make_uint2(hp0, hp1);
                *(uint2*)&sKlo[row * AT_LDS + d0 + j * 4] = make_uint2(lp0, lp1);
                float4 gv = *(const float4*)(vraw + j * 4);
                split2(gv.x, gv.y, hp0, lp0);
                split2(gv.z, gv.w, hp1, lp1);
                *(uint2*)&sVhi[row * AT_LDS + d0 + j * 4] = make_uint2(hp0, hp1);
                *(uint2*)&sVlo[row * AT_LDS + d0 + j * 4] = make_uint2(lp0, lp1);
            }
        }
        __syncthreads();   // split bufs ready; raw[stg] fully consumed

        if (tile + 1 < ntiles) issueKV(tile + 1);   // overlaps compute below

        if (n0 <= warp_max_row) {
            float sacc[8][4];
#pragma unroll
            for (int nt = 0; nt < 8; nt++)
#pragma unroll
                for (int r = 0; r < 4; r++) sacc[nt][r] = 0.f;

            const int kb_row = ((lane >> 4) & 1) * 8 + (lane & 7);
            const int kb_col = ((lane >> 3) & 1) * 8;
#pragma unroll
            for (int kc = 0; kc < 4; kc++) {
                uint32_t kh[8][2], kl[8][2];
#pragma unroll
                for (int np = 0; np < 4; np++) {
                    uint32_t t4[4];
                    uint32_t off = ((np * 16 + kb_row) * AT_LDS + kc * 16 + kb_col) * 2;
                    ldsm4(t4, u_sKhi + off);
                    kh[np * 2 + 0][0] = t4[0]; kh[np * 2 + 0][1] = t4[1];
                    kh[np * 2 + 1][0] = t4[2]; kh[np * 2 + 1][1] = t4[3];
                    ldsm4(t4, u_sKlo + off);
                    kl[np * 2 + 0][0] = t4[0]; kl[np * 2 + 0][1] = t4[1];
                    kl[np * 2 + 1][0] = t4[2]; kl[np * 2 + 1][1] = t4[3];
                }
#pragma unroll
                for (int nt = 0; nt < 8; nt++) {
                    mma16816(sacc[nt], qfh[kc], kh[nt]);
                    mma16816(sacc[nt], qfh[kc], kl[nt]);
                    mma16816(sacc[nt], qfl[kc], kh[nt]);
                }
            }

            if (n0 + 63 > row_lo_g) {
#pragma unroll
                for (int nt = 0; nt < 8; nt++) {
#pragma unroll
                    for (int c = 0; c < 2; c++) {
                        int col = n0 + nt * 8 + par2 + c;
                        if (col > row_lo_g) sacc[nt][c] = -1e30f;
                        if (col > row_lo_g + 8) sacc[nt][2 + c] = -1e30f;
                    }
                }
            } else if (n0 + 63 > row_lo_g + 8) {
#pragma unroll
                for (int nt = 0; nt < 8; nt++)
#pragma unroll
                    for (int c = 0; c < 2; c++) {
                        int col = n0 + nt * 8 + par2 + c;
                        if (col > row_lo_g + 8) sacc[nt][2 + c] = -1e30f;
                    }
            }

            {
                float mx0 = -1e30f, mx1 = -1e30f;
#pragma unroll
                for (int nt = 0; nt < 8; nt++) {
                    mx0 = fmaxf(mx0, fmaxf(sacc[nt][0], sacc[nt][1]));
                    mx1 = fmaxf(mx1, fmaxf(sacc[nt][2], sacc[nt][3]));
                }
                mx0 = fmaxf(mx0, __shfl_xor_sync(0xffffffffu, mx0, 1));
                mx0 = fmaxf(mx0, __shfl_xor_sync(0xffffffffu, mx0, 2));
                mx1 = fmaxf(mx1, __shfl_xor_sync(0xffffffffu, mx1, 1));
                mx1 = fmaxf(mx1, __shfl_xor_sync(0xffffffffu, mx1, 2));
                float mn0 = fmaxf(m_lo, mx0), mn1 = fmaxf(m_hi, mx1);
                float f0 = __expf(m_lo - mn0), f1 = __expf(m_hi - mn1);
                float rs0 = 0.f, rs1 = 0.f;
#pragma unroll
                for (int nt = 0; nt < 8; nt++) {
                    sacc[nt][0] = __expf(sacc[nt][0] - mn0);
                    sacc[nt][1] = __expf(sacc[nt][1] - mn0);
                    sacc[nt][2] = __expf(sacc[nt][2] - mn1);
                    sacc[nt][3] = __expf(sacc[nt][3] - mn1);
                    rs0 += sacc[nt][0] + sacc[nt][1];
                    rs1 += sacc[nt][2] + sacc[nt][3];
                }
                rs0 += __shfl_xor_sync(0xffffffffu, rs0, 1);
                rs0 += __shfl_xor_sync(0xffffffffu, rs0, 2);
                rs1 += __shfl_xor_sync(0xffffffffu, rs1, 1);
                rs1 += __shfl_xor_sync(0xffffffffu, rs1, 2);
                l_lo = l_lo * f0 + rs0;
                l_hi = l_hi * f1 + rs1;
                m_lo = mn0;
                m_hi = mn1;
#pragma unroll
                for (int nt = 0; nt < 8; nt++) {
                    oacc[nt][0] *= f0;
                    oacc[nt][1] *= f0;
                    oacc[nt][2] *= f1;
                    oacc[nt][3] *= f1;
                }
            }

            const int vb_row = ((lane >> 3) & 1) * 8 + (lane & 7);
            const int vb_col = ((lane >> 4) & 1) * 8;
#pragma unroll
            for (int ks = 0; ks < 4; ks++) {
                uint32_t pah[4], pal[4];
                split2(sacc[2 * ks][0], sacc[2 * ks][1], pah[0], pal[0]);
                split2(sacc[2 * ks][2], sacc[2 * ks][3], pah[1], pal[1]);
                split2(sacc[2 * ks + 1][0], sacc[2 * ks + 1][1], pah[2], pal[2]);
                split2(sacc[2 * ks + 1][2], sacc[2 * ks + 1][3], pah[3], pal[3]);

                uint32_t vh[8][2], vl[8][2];
#pragma unroll
                for (int dp = 0; dp < 4; dp++) {
                    uint32_t t4[4];
                    uint32_t off = ((ks * 16 + vb_row) * AT_LDS + dp * 16 + vb_col) * 2;
                    ldsm4t(t4, u_sVhi + off);
                    vh[dp * 2 + 0][0] = t4[0]; vh[dp * 2 + 0][1] = t4[1];
                    vh[dp * 2 + 1][0] = t4[2]; vh[dp * 2 + 1][1] = t4[3];
                    ldsm4t(t4, u_sVlo + off);
                    vl[dp * 2 + 0][0] = t4[0]; vl[dp * 2 + 0][1] = t4[1];
                    vl[dp * 2 + 1][0] = t4[2]; vl[dp * 2 + 1][1] = t4[3];
                }
#pragma unroll
                for (int nt = 0; nt < 8; nt++) {
                    mma16816(oacc[nt], pah, vh[nt]);
                    mma16816(oacc[nt], pah, vl[nt]);
                    mma16816(oacc[nt], pal, vh[nt]);
                }
            }
        }
    }

    float inv0 = 1.f / l_lo, inv1 = 1.f / l_hi;
    float* ob = out + baseOff;
    const int r0 = m0 + w * 16 + quad;
#pragma unroll
    for (int nt = 0; nt < 8; nt++) {
        int col = nt * 8 + par2;
        *(float2*)&ob[(size_t)r0 * EMB_C + col] =
            make_float2(oacc[nt][0] * inv0, oacc[nt][1] * inv0);
        *(float2*)&ob[(size_t)(r0 + 8) * EMB_C + col] =
            make_float2(oacc[nt][2] * inv1, oacc[nt][3] * inv1);
    }
}

// ---------------------------------------------------------------------------
// launch
// ---------------------------------------------------------------------------
extern "C" void kernel_launch(void* const* d_in, const int* in_sizes, int n_in,
                              void* d_out, int out_size) {
    const float* Q  = (const float*)d_in[0];
    const float* K  = (const float*)d_in[1];
    const float* V  = (const float*)d_in[2];
    const float* WQ = (const float*)d_in[3];
    const float* bQ = (const float*)d_in[4];
    const float* WK = (const float*)d_in[5];
    const float* bK = (const float*)d_in[6];
    const float* WV = (const float*)d_in[7];
    const float* bV = (const float*)d_in[8];
    const float* WO = (const float*)d_in[9];
    const float* bO = (const float*)d_in[10];
    float* out = (float*)d_out;

    void *pq, *pk, *pv, *pa, *pwh, *pwl;
    cudaGetSymbolAddress(&pq, g_q);
    cudaGetSymbolAddress(&pk, g_k);
    cudaGetSymbolAddress(&pv, g_v);
    cudaGetSymbolAddress(&pa, g_att);
    cudaGetSymbolAddress(&pwh, g_wthi);
    cudaGetSymbolAddress(&pwl, g_wtlo);
    __nv_bfloat16* whi = (__nv_bfloat16*)pwh;
    __nv_bfloat16* wlo = (__nv_bfloat16*)pwl;
    float* fq = (float*)pq;
    float* fk = (float*)pk;
    float* fv = (float*)pv;
    float* fa = (float*)pa;

    cudaFuncSetAttribute(gemm_batch_kernel,
                         cudaFuncAttributeMaxDynamicSharedMemorySize, GEMM_SMEM_B);
    cudaFuncSetAttribute(attn_tc_kernel,
                         cudaFuncAttributeMaxDynamicSharedMemorySize, AT_SMEM_B);

    // split all 4 weight matrices (slots: 0=WQ, 1=WK, 2=WV, 3=WO)
    wsplit_all_kernel<<<dim3(EMB_C / 32, EMB_C / 32, 4), dim3(32, 8)>>>(
        WQ, WK, WV, WO, whi, wlo);

    // Q, K, V projections in one batched launch
    gemm_batch_kernel<<<dim3(EMB_C / 128, MROWS / 128, 3), 256, GEMM_SMEM_B>>>(
        Q, K, V, whi, wlo, bQ, bK, bV, fq, fk, fv, 0);

    // attention (tensor core, pipelined K/V staging)
    dim3 ga(L_C / 128, HEADS_C, B_C);   // (16, 16, 4)
    attn_tc_kernel<<<ga, 256, AT_SMEM_B>>>(fq, fk, fv, fa);

    // O projection (slot 3)
    gemm_batch_kernel<<<dim3(EMB_C / 128, MROWS / 128, 1), 256, GEMM_SMEM_B>>>(
        fa, fa, fa, whi, wlo, bO, bO, bO, out, out, out, 3);
}

// round 12
// speedup vs baseline: 1.3799x; 1.0839x over previous
#include <cuda_runtime.h>
#include <cuda_bf16.h>
#include <math.h>
#include <cstdint>

// Problem constants (fixed by dataset)
#define B_C   4
#define L_C   2048
#define EMB_C 1024
#define HEADS_C 16
#define DH    64
#define MROWS (B_C * L_C)          // 8192
#define SCALE_C 0.125f             // 1/sqrt(64)

// ---------------------------------------------------------------------------
// Scratch (allocation-free rule: __device__ globals)
// ---------------------------------------------------------------------------
__device__ __nv_bfloat16 g_qhi[MROWS * EMB_C];
__device__ __nv_bfloat16 g_qlo[MROWS * EMB_C];
__device__ __nv_bfloat16 g_khi[MROWS * EMB_C];
__device__ __nv_bfloat16 g_klo[MROWS * EMB_C];
__device__ __nv_bfloat16 g_vhi[MROWS * EMB_C];
__device__ __nv_bfloat16 g_vlo[MROWS * EMB_C];
__device__ float g_att[MROWS * EMB_C];
__device__ __nv_bfloat16 g_wthi[4 * EMB_C * EMB_C];  // W^T split (hi) [slot][N,K]
__device__ __nv_bfloat16 g_wtlo[4 * EMB_C * EMB_C];  // W^T split (lo) [slot][N,K]

// ---------------------------------------------------------------------------
// Warp-MMA helpers (arch-portable PTX: ldmatrix + mma.sync m16n8k16 bf16)
// ---------------------------------------------------------------------------
__device__ __forceinline__ uint32_t smem_u32(const void* p) {
    uint32_t a;
    asm("{ .reg .u64 t; cvta.to.shared.u64 t, %1; cvt.u32.u64 %0, t; }"
        : "=r"(a) : "l"(p));
    return a;
}
__device__ __forceinline__ void ldsm4(uint32_t* r, uint32_t addr) {
    asm volatile("ldmatrix.sync.aligned.m8n8.x4.shared.b16 {%0,%1,%2,%3}, [%4];"
                 : "=r"(r[0]), "=r"(r[1]), "=r"(r[2]), "=r"(r[3]) : "r"(addr));
}
__device__ __forceinline__ void ldsm4t(uint32_t* r, uint32_t addr) {
    asm volatile("ldmatrix.sync.aligned.m8n8.x4.trans.shared.b16 {%0,%1,%2,%3}, [%4];"
                 : "=r"(r[0]), "=r"(r[1]), "=r"(r[2]), "=r"(r[3]) : "r"(addr));
}
__device__ __forceinline__ void mma16816(float* c, const uint32_t* a, const uint32_t* b) {
    asm volatile(
        "mma.sync.aligned.m16n8k16.row.col.f32.bf16.bf16.f32 "
        "{%0,%1,%2,%3}, {%4,%5,%6,%7}, {%8,%9}, {%0,%1,%2,%3};"
        : "+f"(c[0]), "+f"(c[1]), "+f"(c[2]), "+f"(c[3])
        : "r"(a[0]), "r"(a[1]), "r"(a[2]), "r"(a[3]), "r"(b[0]), "r"(b[1]));
}
__device__ __forceinline__ void cpasync16(uint32_t saddr, const void* gptr) {
    asm volatile("cp.async.cg.shared.global [%0], [%1], 16;"
                 :: "r"(saddr), "l"(gptr) : "memory");
}
#define CP_COMMIT() asm volatile("cp.async.commit_group;" ::: "memory")
#define CP_WAIT0()  asm volatile("cp.async.wait_group 0;" ::: "memory")
#define CP_WAIT1()  asm volatile("cp.async.wait_group 1;" ::: "memory")

// split two fp32 into packed bf16x2 hi and lo parts
__device__ __forceinline__ void split2(float a, float b, uint32_t& hp, uint32_t& lp) {
    __nv_bfloat16 ha = __float2bfloat16(a), hb = __float2bfloat16(b);
    __nv_bfloat16 la = __float2bfloat16(a - __bfloat162float(ha));
    __nv_bfloat16 lb = __float2bfloat16(b - __bfloat162float(hb));
    __nv_bfloat162 h2(ha, hb), l2(la, lb);
    hp = *(uint32_t*)&h2;
    lp = *(uint32_t*)&l2;
}

// ---------------------------------------------------------------------------
// weight transpose + split, all 4 weights in one launch (slot = blockIdx.z)
// ---------------------------------------------------------------------------
__global__ __launch_bounds__(256)
void wsplit_all_kernel(const float* __restrict__ W0, const float* __restrict__ W1,
                       const float* __restrict__ W2, const float* __restrict__ W3,
                       __nv_bfloat16* __restrict__ hi, __nv_bfloat16* __restrict__ lo) {
    __shared__ float t[32][33];
    const int z = blockIdx.z;
    const float* W = (z == 0) ? W0 : (z == 1) ? W1 : (z == 2) ? W2 : W3;
    __nv_bfloat16* hz = hi + (size_t)z * EMB_C * EMB_C;
    __nv_bfloat16* lz = lo + (size_t)z * EMB_C * EMB_C;
    int tx = threadIdx.x, ty = threadIdx.y;           // 32 x 8
    int n0 = blockIdx.x * 32, k0 = blockIdx.y * 32;
#pragma unroll
    for (int r = ty; r < 32; r += 8)
        t[r][tx] = W[(size_t)(k0 + r) * EMB_C + n0 + tx];
    __syncthreads();
#pragma unroll
    for (int r = ty; r < 32; r += 8) {
        float v = t[tx][r];                           // W[k0+tx][n0+r]
        __nv_bfloat16 h = __float2bfloat16(v);
        size_t o = (size_t)(n0 + r) * EMB_C + k0 + tx;
        hz[o] = h;
        lz[o] = __float2bfloat16(v - __bfloat162float(h));
    }
}

// ---------------------------------------------------------------------------
// Fused mma.sync GEMM, batched over blockIdx.z (selects A/bias/C/weight-slot).
// C = A[M,K](fp32, split in-kernel) @ (Whi+Wlo)^T + bias  [bf16, 3 products]
// Output: fp32 C (split_out=0) or bf16 hi/lo pair with post-scale (split_out=1).
// CTA tile 128x128, BK=32, 8 warps. B: 3-stage cp.async. 2 CTAs/SM.
// ---------------------------------------------------------------------------
#define LDS_T 40
#define TILE_E (128 * LDS_T)
#define GEMM_SMEM_B (10 * TILE_E * 2)   // sA 4 + sB 6 tiles = 102400 bytes

__global__ __launch_bounds__(256, 2)
void gemm_batch_kernel(const float* __restrict__ A0, const float* __restrict__ A1,
                       const float* __restrict__ A2,
                       const __nv_bfloat16* __restrict__ whi_all,
                       const __nv_bfloat16* __restrict__ wlo_all,
                       const float* __restrict__ b0, const float* __restrict__ b1,
                       const float* __restrict__ b2,
                       float* __restrict__ C0,
                       __nv_bfloat16* __restrict__ H0, __nv_bfloat16* __restrict__ L0,
                       __nv_bfloat16* __restrict__ H1, __nv_bfloat16* __restrict__ L1,
                       __nv_bfloat16* __restrict__ H2, __nv_bfloat16* __restrict__ L2,
                       int wslot0, int split_out, float osc0) {
    extern __shared__ __nv_bfloat16 smbf[];
    __nv_bfloat16* sA = smbf;                 // 4 x TILE_E (2 bufs x hi/lo)
    __nv_bfloat16* sB = smbf + 4 * TILE_E;    // 6 x TILE_E (3 stages x hi/lo)

    const int z = blockIdx.z;
    const float* A    = (z == 0) ? A0 : (z == 1) ? A1 : A2;
    const float* bias = (z == 0) ? b0 : (z == 1) ? b1 : b2;
    const size_t woff = (size_t)(wslot0 + z) * EMB_C * EMB_C;
    const __nv_bfloat16* Bhi = whi_all + woff;
    const __nv_bfloat16* Blo = wlo_all + woff;
    const int Kd = EMB_C, Nd = EMB_C;

    const int tid = threadIdx.x;
    const int lane = tid & 31;
    const int wid = tid >> 5;
    const int warp_m = wid & 1;
    const int warp_n = wid >> 1;
    const int m0 = blockIdx.y * 128;
    const int n0 = blockIdx.x * 128;

    float acc[4][4][4];
#pragma unroll
    for (int mi = 0; mi < 4; mi++)
#pragma unroll
        for (int ni = 0; ni < 4; ni++)
#pragma unroll
            for (int r = 0; r < 4; r++) acc[mi][ni][r] = 0.f;

    const int a_row = (lane & 15);
    const int a_co  = (lane >> 4) << 3;
    const int b_rsel = (lane >> 4);
    const int b_row  = (lane & 7);
    const int b_co   = ((lane >> 3) & 1) << 3;

    const int st_row = tid >> 1;
    const int st_c0  = (tid & 1) << 4;

    float4 areg[4];
    const int nch = Kd / 32;

    auto issueB = [&](int c) {
        int stage = c - (c / 3) * 3;
        int k0 = c * 32;
#pragma unroll
        for (int t = 0; t < 4; t++) {
            int i = tid + t * 256;
            int sp = i >> 9, rem = i & 511, row = rem >> 2, seg = (rem & 3) << 3;
            const __nv_bfloat16* src = (sp ? Blo : Bhi) + (size_t)(n0 + row) * Kd + k0 + seg;
            cpasync16(smem_u32(sB + (stage * 2 + sp) * TILE_E + row * LDS_T + seg), src);
        }
        CP_COMMIT();
    };

    issueB(0);
    issueB(1);
    {
        const float* asrc = A + (size_t)(m0 + st_row) * Kd + st_c0;
#pragma unroll
        for (int j = 0; j < 4; j++) areg[j] = *(const float4*)(asrc + j * 4);
#pragma unroll
        for (int j = 0; j < 4; j++) {
            uint32_t hp0, lp0, hp1, lp1;
            split2(areg[j].x, areg[j].y, hp0, lp0);
            split2(areg[j].z, areg[j].w, hp1, lp1);
            *(uint2*)&sA[0 * TILE_E + st_row * LDS_T + st_c0 + j * 4] = make_uint2(hp0, hp1);
            *(uint2*)&sA[1 * TILE_E + st_row * LDS_T + st_c0 + j * 4] = make_uint2(lp0, lp1);
        }
    }

    for (int chunk = 0; chunk < nch; chunk++) {
        const int cur = chunk & 1;
        const int nxt = cur ^ 1;
        const int stage = chunk - (chunk / 3) * 3;
        const bool has_next = (chunk + 1) < nch;

        if (chunk == nch - 1) { CP_WAIT0(); } else { CP_WAIT1(); }
        __syncthreads();

        if (chunk + 2 < nch) issueB(chunk + 2);
        if (has_next) {
            const float* asrc = A + (size_t)(m0 + st_row) * Kd + (chunk + 1) * 32 + st_c0;
#pragma unroll
            for (int j = 0; j < 4; j++) areg[j] = *(const float4*)(asrc + j * 4);
        }

        const __nv_bfloat16* cAh = sA + (cur * 2 + 0) * TILE_E;
        const __nv_bfloat16* cAl = sA + (cur * 2 + 1) * TILE_E;
        const __nv_bfloat16* cBh = sB + (stage * 2 + 0) * TILE_E;
        const __nv_bfloat16* cBl = sB + (stage * 2 + 1) * TILE_E;
#pragma unroll
        for (int ks = 0; ks < 2; ks++) {
            uint32_t bf[2][4][2];
#pragma unroll
            for (int np = 0; np < 2; np++) {
                int rowe = (warp_n * 32 + (np * 2 + b_rsel) * 8 + b_row) * LDS_T
                           + ks * 16 + b_co;
                uint32_t r4[4];
                ldsm4(r4, smem_u32(cBh) + rowe * 2);
                bf[0][np * 2 + 0][0] = r4[0]; bf[0][np * 2 + 0][1] = r4[1];
                bf[0][np * 2 + 1][0] = r4[2]; bf[0][np * 2 + 1][1] = r4[3];
                ldsm4(r4, smem_u32(cBl) + rowe * 2);
                bf[1][np * 2 + 0][0] = r4[0]; bf[1][np * 2 + 0][1] = r4[1];
                bf[1][np * 2 + 1][0] = r4[2]; bf[1][np * 2 + 1][1] = r4[3];
            }
#pragma unroll
            for (int mi = 0; mi < 4; mi++) {
                uint32_t af[2][4];
                int rowe = (warp_m * 64 + mi * 16 + a_row) * LDS_T + ks * 16 + a_co;
                ldsm4(af[0], smem_u32(cAh) + rowe * 2);
                ldsm4(af[1], smem_u32(cAl) + rowe * 2);
#pragma unroll
                for (int ni = 0; ni < 4; ni++) {
                    mma16816(acc[mi][ni], af[0], bf[0][ni]);  // hi*hi
                    mma16816(acc[mi][ni], af[0], bf[1][ni]);  // hi*lo
                    mma16816(acc[mi][ni], af[1], bf[0][ni]);  // lo*hi
                }
            }
        }

        if (has_next) {
#pragma unroll
            for (int j = 0; j < 4; j++) {
                uint32_t hp0, lp0, hp1, lp1;
                split2(areg[j].x, areg[j].y, hp0, lp0);
                split2(areg[j].z, areg[j].w, hp1, lp1);
                *(uint2*)&sA[(nxt * 2 + 0) * TILE_E + st_row * LDS_T + st_c0 + j * 4] =
                    make_uint2(hp0, hp1);
                *(uint2*)&sA[(nxt * 2 + 1) * TILE_E + st_row * LDS_T + st_c0 + j * 4] =
                    make_uint2(lp0, lp1);
            }
        }
    }

    // ---- epilogue ----
    if (!split_out) {
#pragma unroll
        for (int mi = 0; mi < 4; mi++) {
#pragma unroll
            for (int ni = 0; ni < 4; ni++) {
                int col = n0 + warp_n * 32 + ni * 8 + (lane & 3) * 2;
                float2 bv = *(const float2*)&bias[col];
                int r0 = m0 + warp_m * 64 + mi * 16 + (lane >> 2);
                float2 o0 = make_float2(acc[mi][ni][0] + bv.x, acc[mi][ni][1] + bv.y);
                float2 o1 = make_float2(acc[mi][ni][2] + bv.x, acc[mi][ni][3] + bv.y);
                *(float2*)&C0[(size_t)r0 * Nd + col] = o0;
                *(float2*)&C0[(size_t)(r0 + 8) * Nd + col] = o1;
            }
        }
    } else {
        __nv_bfloat16* Chi = (z == 0) ? H0 : (z == 1) ? H1 : H2;
        __nv_bfloat16* Clo = (z == 0) ? L0 : (z == 1) ? L1 : L2;
        const float osc = (z == 0) ? osc0 : 1.f;
#pragma unroll
        for (int mi = 0; mi < 4; mi++) {
#pragma unroll
            for (int ni = 0; ni < 4; ni++) {
                int col = n0 + warp_n * 32 + ni * 8 + (lane & 3) * 2;
                float2 bv = *(const float2*)&bias[col];
                int r0 = m0 + warp_m * 64 + mi * 16 + (lane >> 2);
                uint32_t hp, lp;
                split2((acc[mi][ni][0] + bv.x) * osc, (acc[mi][ni][1] + bv.y) * osc, hp, lp);
                *(uint32_t*)&Chi[(size_t)r0 * Nd + col] = hp;
                *(uint32_t*)&Clo[(size_t)r0 * Nd + col] = lp;
                split2((acc[mi][ni][2] + bv.x) * osc, (acc[mi][ni][3] + bv.y) * osc, hp, lp);
                *(uint32_t*)&Chi[(size_t)(r0 + 8) * Nd + col] = hp;
                *(uint32_t*)&Clo[(size_t)(r0 + 8) * Nd + col] = lp;
            }
        }
    }
}

// ---------------------------------------------------------------------------
// Tensor-core flash attention (causal). BM=128, BN=64, D=64, 8 warps.
// Q/K/V arrive pre-split bf16 hi/lo; cp.async straight into ldsm layout.
// 2-stage ping-pong (K/V), one barrier per tile. 2 CTAs/SM.
// ---------------------------------------------------------------------------
#define AT_LDS 72
#define AT_SEG (64 * AT_LDS)                    // elems per buffer
#define AT_SMEM_B (2 * 4 * AT_SEG * 2)          // 2 stages x 4 bufs x bf16 = 73728

__global__ __launch_bounds__(256, 2)
void attn_tc_kernel(const __nv_bfloat16* __restrict__ qhi,
                    const __nv_bfloat16* __restrict__ qlo,
                    const __nv_bfloat16* __restrict__ khi,
                    const __nv_bfloat16* __restrict__ klo,
                    const __nv_bfloat16* __restrict__ vhi,
                    const __nv_bfloat16* __restrict__ vlo,
                    float* __restrict__ out) {
    extern __shared__ __align__(16) __nv_bfloat16 smb[];
    // stage s block: [Khi, Klo, Vhi, Vlo] each AT_SEG elems
    const int tid = threadIdx.x;
    const int lane = tid & 31;
    const int w = tid >> 5;
    const int quad = lane >> 2;
    const int par2 = (lane & 3) * 2;

    const int m0 = (gridDim.x - 1 - blockIdx.x) * 128;   // heavy tiles first
    const int h  = blockIdx.y;
    const int b  = blockIdx.z;
    const size_t baseOff = (size_t)b * L_C * EMB_C + (size_t)h * DH;

    const uint32_t u_sm = smem_u32(smb);

    const int ntiles = m0 / 64 + 2;

    // per-tile K/V prefetch: 4 buffers x 64 rows x 8 segs = 2048 cp.async
    auto issueKV = [&](int tile) {
        int stg = tile & 1;
        int n0 = tile * 64;
        const __nv_bfloat16* srcs[4] = {khi + baseOff, klo + baseOff,
                                        vhi + baseOff, vlo + baseOff};
#pragma unroll
        for (int t = 0; t < 8; t++) {
            int i = tid + t * 256;
            int buf = i >> 9, rem = i & 511, row = rem >> 3, seg = (rem & 7) << 3;
            const __nv_bfloat16* src = srcs[buf] + (size_t)(n0 + row) * EMB_C + seg;
            cpasync16(u_sm + ((stg * 4 + buf) * AT_SEG + row * AT_LDS + seg) * 2, src);
        }
        CP_COMMIT();
    };

    // ---- prologue: KV tile 0 (stage 0) + Q staged in stage-1 block ----
    issueKV(0);
    {
        // Q hi -> stage1 bufs 0-1 area (128 rows), Q lo -> stage1 bufs 2-3 area
        const __nv_bfloat16* qh = qhi + baseOff;
        const __nv_bfloat16* ql = qlo + baseOff;
#pragma unroll
        for (int t = 0; t < 8; t++) {
            int i = tid + t * 256;
            int sp = i >> 10, rem = i & 1023, row = rem >> 3, seg = (rem & 7) << 3;
            const __nv_bfloat16* src = (sp ? ql : qh) + (size_t)(m0 + row) * EMB_C + seg;
            cpasync16(u_sm + ((4 + sp * 2) * AT_SEG + row * AT_LDS + seg) * 2, src);
        }
        CP_COMMIT();
    }
    CP_WAIT0();
    __syncthreads();

    uint32_t qfh[4][4], qfl[4][4];
    {
        int r = w * 16 + (lane & 15);
        int c = (lane >> 4) * 8;
#pragma unroll
        for (int kc = 0; kc < 4; kc++) {
            ldsm4(qfh[kc], u_sm + (4 * AT_SEG + r * AT_LDS + kc * 16 + c) * 2);
            ldsm4(qfl[kc], u_sm + (6 * AT_SEG + r * AT_LDS + kc * 16 + c) * 2);
        }
    }
    __syncthreads();   // Q fragments in regs; stage-1 block free for KV

    float oacc[8][4];
#pragma unroll
    for (int nt = 0; nt < 8; nt++)
#pragma unroll
        for (int r = 0; r < 4; r++) oacc[nt][r] = 0.f;
    float m_lo = -1e30f, m_hi = -1e30f, l_lo = 0.f, l_hi = 0.f;

    const int row_lo_g = m0 + w * 16 + quad;
    const int warp_max_row = m0 + w * 16 + 15;

    for (int tile = 0; tile < ntiles; tile++) {
        const int n0 = tile * 64;
        const int stg = tile & 1;

        CP_WAIT0();
        __syncthreads();   // KV[tile] ready; all warps done reading stage (tile+1)&1

        if (tile + 1 < ntiles) issueKV(tile + 1);   // overlaps compute below

        if (n0 <= warp_max_row) {
            const uint32_t u_sKhi = u_sm + (stg * 4 + 0) * AT_SEG * 2;
            const uint32_t u_sKlo = u_sm + (stg * 4 + 1) * AT_SEG * 2;
            const uint32_t u_sVhi = u_sm + (stg * 4 + 2) * AT_SEG * 2;
            const uint32_t u_sVlo = u_sm + (stg * 4 + 3) * AT_SEG * 2;

            float sacc[8][4];
#pragma unroll
            for (int nt = 0; nt < 8; nt++)
#pragma unroll
                for (int r = 0; r < 4; r++) sacc[nt][r] = 0.f;

            const int kb_row = ((lane >> 4) & 1) * 8 + (lane & 7);
            const int kb_col = ((lane >> 3) & 1) * 8;
#pragma unroll
            for (int kc = 0; kc < 4; kc++) {
                uint32_t kh[8][2], kl[8][2];
#pragma unroll
                for (int np = 0; np < 4; np++) {
                    uint32_t t4[4];
                    uint32_t off = ((np * 16 + kb_row) * AT_LDS + kc * 16 + kb_col) * 2;
                    ldsm4(t4, u_sKhi + off);
                    kh[np * 2 + 0][0] = t4[0]; kh[np * 2 + 0][1] = t4[1];
                    kh[np * 2 + 1][0] = t4[2]; kh[np * 2 + 1][1] = t4[3];
                    ldsm4(t4, u_sKlo + off);
                    kl[np * 2 + 0][0] = t4[0]; kl[np * 2 + 0][1] = t4[1];
                    kl[np * 2 + 1][0] = t4[2]; kl[np * 2 + 1][1] = t4[3];
                }
#pragma unroll
                for (int nt = 0; nt < 8; nt++) {
                    mma16816(sacc[nt], qfh[kc], kh[nt]);
                    mma16816(sacc[nt], qfh[kc], kl[nt]);
                    mma16816(sacc[nt], qfl[kc], kh[nt]);
                }
            }

            if (n0 + 63 > row_lo_g) {
#pragma unroll
                for (int nt = 0; nt < 8; nt++) {
#pragma unroll
                    for (int c = 0; c < 2; c++) {
                        int col = n0 + nt * 8 + par2 + c;
                        if (col > row_lo_g) sacc[nt][c] = -1e30f;
                        if (col > row_lo_g + 8) sacc[nt][2 + c] = -1e30f;
                    }
                }
            } else if (n0 + 63 > row_lo_g + 8) {
#pragma unroll
                for (int nt = 0; nt < 8; nt++)
#pragma unroll
                    for (int c = 0; c < 2; c++) {
                        int col = n0 + nt * 8 + par2 + c;
                        if (col > row_lo_g + 8) sacc[nt][2 + c] = -1e30f;
                    }
            }

            {
                float mx0 = -1e30f, mx1 = -1e30f;
#pragma unroll
                for (int nt = 0; nt < 8; nt++) {
                    mx0 = fmaxf(mx0, fmaxf(sacc[nt][0], sacc[nt][1]));
                    mx1 = fmaxf(mx1, fmaxf(sacc[nt][2], sacc[nt][3]));
                }
                mx0 = fmaxf(mx0, __shfl_xor_sync(0xffffffffu, mx0, 1));
                mx0 = fmaxf(mx0, __shfl_xor_sync(0xffffffffu, mx0, 2));
                mx1 = fmaxf(mx1, __shfl_xor_sync(0xffffffffu, mx1, 1));
                mx1 = fmaxf(mx1, __shfl_xor_sync(0xffffffffu, mx1, 2));
                float mn0 = fmaxf(m_lo, mx0), mn1 = fmaxf(m_hi, mx1);
                float f0 = __expf(m_lo - mn0), f1 = __expf(m_hi - mn1);
                float rs0 = 0.f, rs1 = 0.f;
#pragma unroll
                for (int nt = 0; nt < 8; nt++) {
                    sacc[nt][0] = __expf(sacc[nt][0] - mn0);
                    sacc[nt][1] = __expf(sacc[nt][1] - mn0);
                    sacc[nt][2] = __expf(sacc[nt][2] - mn1);
                    sacc[nt][3] = __expf(sacc[nt][3] - mn1);
                    rs0 += sacc[nt][0] + sacc[nt][1];
                    rs1 += sacc[nt][2] + sacc[nt][3];
                }
                rs0 += __shfl_xor_sync(0xffffffffu, rs0, 1);
                rs0 += __shfl_xor_sync(0xffffffffu, rs0, 2);
                rs1 += __shfl_xor_sync(0xffffffffu, rs1, 1);
                rs1 += __shfl_xor_sync(0xffffffffu, rs1, 2);
                l_lo = l_lo * f0 + rs0;
                l_hi = l_hi * f1 + rs1;
                m_lo = mn0;
                m_hi = mn1;
#pragma unroll
                for (int nt = 0; nt < 8; nt++) {
                    oacc[nt][0] *= f0;
                    oacc[nt][1] *= f0;
                    oacc[nt][2] *= f1;
                    oacc[nt][3] *= f1;
                }
            }

            const int vb_row = ((lane >> 3) & 1) * 8 + (lane & 7);
            const int vb_col = ((lane >> 4) & 1) * 8;
#pragma unroll
            for (int ks = 0; ks < 4; ks++) {
                uint32_t pah[4], pal[4];
                split2(sacc[2 * ks][0], sacc[2 * ks][1], pah[0], pal[0]);
                split2(sacc[2 * ks][2], sacc[2 * ks][3], pah[1], pal[1]);
                split2(sacc[2 * ks + 1][0], sacc[2 * ks + 1][1], pah[2], pal[2]);
                split2(sacc[2 * ks + 1][2], sacc[2 * ks + 1][3], pah[3], pal[3]);

                uint32_t vh[8][2], vl[8][2];
#pragma unroll
                for (int dp = 0; dp < 4; dp++) {
                    uint32_t t4[4];
                    uint32_t off = ((ks * 16 + vb_row) * AT_LDS + dp * 16 + vb_col) * 2;
                    ldsm4t(t4, u_sVhi + off);
                    vh[dp * 2 + 0][0] = t4[0]; vh[dp * 2 + 0][1] = t4[1];
                    vh[dp * 2 + 1][0] = t4[2]; vh[dp * 2 + 1][1] = t4[3];
                    ldsm4t(t4, u_sVlo + off);
                    vl[dp * 2 + 0][0] = t4[0]; vl[dp * 2 + 0][1] = t4[1];
                    vl[dp * 2 + 1][0] = t4[2]; vl[dp * 2 + 1][1] = t4[3];
                }
#pragma unroll
                for (int nt = 0; nt < 8; nt++) {
                    mma16816(oacc[nt], pah, vh[nt]);
                    mma16816(oacc[nt], pah, vl[nt]);
                    mma16816(oacc[nt], pal, vh[nt]);
                }
            }
        }
    }

    float inv0 = 1.f / l_lo, inv1 = 1.f / l_hi;
    float* ob = out + baseOff;
    const int r0 = m0 + w * 16 + quad;
#pragma unroll
    for (int nt = 0; nt < 8; nt++) {
        int col = nt * 8 + par2;
        *(float2*)&ob[(size_t)r0 * EMB_C + col] =
            make_float2(oacc[nt][0] * inv0, oacc[nt][1] * inv0);
        *(float2*)&ob[(size_t)(r0 + 8) * EMB_C + col] =
            make_float2(oacc[nt][2] * inv1, oacc[nt][3] * inv1);
    }
}

// ---------------------------------------------------------------------------
// launch
// ---------------------------------------------------------------------------
extern "C" void kernel_launch(void* const* d_in, const int* in_sizes, int n_in,
                              void* d_out, int out_size) {
    const float* Q  = (const float*)d_in[0];
    const float* K  = (const float*)d_in[1];
    const float* V  = (const float*)d_in[2];
    const float* WQ = (const float*)d_in[3];
    const float* bQ = (const float*)d_in[4];
    const float* WK = (const float*)d_in[5];
    const float* bK = (const float*)d_in[6];
    const float* WV = (const float*)d_in[7];
    const float* bV = (const float*)d_in[8];
    const float* WO = (const float*)d_in[9];
    const float* bO = (const float*)d_in[10];
    float* out = (float*)d_out;

    void *pqh, *pql, *pkh, *pkl, *pvh, *pvl, *pa, *pwh, *pwl;
    cudaGetSymbolAddress(&pqh, g_qhi);
    cudaGetSymbolAddress(&pql, g_qlo);
    cudaGetSymbolAddress(&pkh, g_khi);
    cudaGetSymbolAddress(&pkl, g_klo);
    cudaGetSymbolAddress(&pvh, g_vhi);
    cudaGetSymbolAddress(&pvl, g_vlo);
    cudaGetSymbolAddress(&pa, g_att);
    cudaGetSymbolAddress(&pwh, g_wthi);
    cudaGetSymbolAddress(&pwl, g_wtlo);
    __nv_bfloat16* whi = (__nv_bfloat16*)pwh;
    __nv_bfloat16* wlo = (__nv_bfloat16*)pwl;
    float* fa = (float*)pa;

    cudaFuncSetAttribute(gemm_batch_kernel,
                         cudaFuncAttributeMaxDynamicSharedMemorySize, GEMM_SMEM_B);
    cudaFuncSetAttribute(attn_tc_kernel,
                         cudaFuncAttributeMaxDynamicSharedMemorySize, AT_SMEM_B);

    // split all 4 weight matrices (slots: 0=WQ, 1=WK, 2=WV, 3=WO)
    wsplit_all_kernel<<<dim3(EMB_C / 32, EMB_C / 32, 4), dim3(32, 8)>>>(
        WQ, WK, WV, WO, whi, wlo);

    // Q, K, V projections -> pre-split bf16 hi/lo (Q pre-scaled by 1/sqrt(D))
    gemm_batch_kernel<<<dim3(EMB_C / 128, MROWS / 128, 3), 256, GEMM_SMEM_B>>>(
        Q, K, V, whi, wlo, bQ, bK, bV, nullptr,
        (__nv_bfloat16*)pqh, (__nv_bfloat16*)pql,
        (__nv_bfloat16*)pkh, (__nv_bfloat16*)pkl,
        (__nv_bfloat16*)pvh, (__nv_bfloat16*)pvl, 0, 1, SCALE_C);

    // attention (tensor core, convert-free pipelined K/V)
    dim3 ga(L_C / 128, HEADS_C, B_C);   // (16, 16, 4)
    attn_tc_kernel<<<ga, 256, AT_SMEM_B>>>(
        (const __nv_bfloat16*)pqh, (const __nv_bfloat16*)pql,
        (const __nv_bfloat16*)pkh, (const __nv_bfloat16*)pkl,
        (const __nv_bfloat16*)pvh, (const __nv_bfloat16*)pvl, fa);

    // O projection (slot 3, fp32 out)
    gemm_batch_kernel<<<dim3(EMB_C / 128, MROWS / 128, 1), 256, GEMM_SMEM_B>>>(
        fa, fa, fa, whi, wlo, bO, bO, bO, out,
        nullptr, nullptr, nullptr, nullptr, nullptr, nullptr, 3, 0, 1.f);
}